// round 1
// baseline (speedup 1.0000x reference)
#include <cuda_runtime.h>

#define BATCH 1024
#define DIM   512
#define QSZ   32768
#define QOFF  (QSZ - BATCH)   // 31744

#define BM 64
#define BN 64
#define BK 16
#define NTILES (QSZ / BN)     // 512

struct __align__(16) Top2 { float k1; int i1; float k2; int i2; };

__device__ float g_qnorm[QSZ];
__device__ Top2  g_partial[(size_t)BATCH * NTILES];   // 8 MB scratch

__device__ __forceinline__ const float* queue_row(const float* x, const float* qp, int j) {
    // queue[j] = queue_prev[j + BATCH] for j < QOFF, else x[j - QOFF]
    return (j < QOFF) ? (qp + (size_t)(j + BATCH) * DIM)
                      : (x  + (size_t)(j - QOFF) * DIM);
}

__device__ __forceinline__ bool lex_less(float ak, int ai, float bk, int bi) {
    return ak < bk || (ak == bk && ai < bi);
}

// merge top2 (ok1,oi1,ok2,oi2) into (k1,i1,k2,i2); both lists sorted
__device__ __forceinline__ void merge_top2(float& k1, int& i1, float& k2, int& i2,
                                           float ok1, int oi1, float ok2, int oi2) {
    if (lex_less(ok1, oi1, k1, i1)) {
        if (lex_less(ok2, oi2, k1, i1)) { k2 = ok2; i2 = oi2; }
        else                            { k2 = k1;  i2 = i1;  }
        k1 = ok1; i1 = oi1;
    } else {
        if (lex_less(ok1, oi1, k2, i2)) { k2 = ok1; i2 = oi1; }
    }
}

// ---------------------------------------------------------------------------
// Kernel 1: qnorm[j] = ||queue[j]||^2.  One warp per queue row.
// ---------------------------------------------------------------------------
__global__ void __launch_bounds__(256) qnorm_kernel(const float* __restrict__ x,
                                                    const float* __restrict__ qp) {
    int warp = (blockIdx.x * blockDim.x + threadIdx.x) >> 5;
    int lane = threadIdx.x & 31;
    if (warp >= QSZ) return;
    const float4* r4 = (const float4*)queue_row(x, qp, warp);
    float s = 0.f;
#pragma unroll
    for (int i = 0; i < 4; i++) {
        float4 v = r4[lane + 32 * i];
        s += v.x * v.x + v.y * v.y + v.z * v.z + v.w * v.w;
    }
#pragma unroll
    for (int o = 16; o; o >>= 1) s += __shfl_xor_sync(0xffffffffu, s, o);
    if (lane == 0) g_qnorm[warp] = s;
}

// ---------------------------------------------------------------------------
// Kernel 2: 64x64x16 fp32 GEMM tile (S = x @ queue^T) with fused per-row
// top-2 of key = qnorm[j] - 2*S[i][j].  Writes one Top2 partial per
// (row, col-tile).
// ---------------------------------------------------------------------------
__global__ void __launch_bounds__(256) gemm_top2_kernel(const float* __restrict__ x,
                                                        const float* __restrict__ qp) {
    __shared__ __align__(16) float As[BK][BM + 4];
    __shared__ __align__(16) float Bs[BK][BN + 4];

    const int tid = threadIdx.x;
    const int tx  = tid & 15;        // column group (4 cols each)
    const int ty  = tid >> 4;        // row group (4 rows each)
    const int m0  = blockIdx.y * BM;
    const int n0  = blockIdx.x * BN;

    const int lrow = tid >> 2;         // 0..63  (tile row for loading)
    const int lc4  = (tid & 3) * 4;    // 0,4,8,12 (k offset for loading)

    const float* arow = x + (size_t)(m0 + lrow) * DIM + lc4;
    const float* brow = queue_row(x, qp, n0 + lrow) + lc4;

    float acc[4][4] = {};

    for (int kt = 0; kt < DIM; kt += BK) {
        float4 a = *(const float4*)(arow + kt);
        float4 b = *(const float4*)(brow + kt);
        As[lc4 + 0][lrow] = a.x; As[lc4 + 1][lrow] = a.y;
        As[lc4 + 2][lrow] = a.z; As[lc4 + 3][lrow] = a.w;
        Bs[lc4 + 0][lrow] = b.x; Bs[lc4 + 1][lrow] = b.y;
        Bs[lc4 + 2][lrow] = b.z; Bs[lc4 + 3][lrow] = b.w;
        __syncthreads();
#pragma unroll
        for (int k = 0; k < BK; k++) {
            float4 a4 = *(const float4*)&As[k][ty * 4];
            float4 b4 = *(const float4*)&Bs[k][tx * 4];
            float av[4] = {a4.x, a4.y, a4.z, a4.w};
            float bv[4] = {b4.x, b4.y, b4.z, b4.w};
#pragma unroll
            for (int r = 0; r < 4; r++)
#pragma unroll
                for (int c = 0; c < 4; c++)
                    acc[r][c] = fmaf(av[r], bv[c], acc[r][c]);
        }
        __syncthreads();
    }

    // Epilogue: per-row top-2 of key = qnorm[j] - 2*acc over this 64-col tile.
    const float INF = __int_as_float(0x7f800000);
    float qn[4];
#pragma unroll
    for (int c = 0; c < 4; c++) qn[c] = g_qnorm[n0 + tx * 4 + c];

#pragma unroll
    for (int r = 0; r < 4; r++) {
        float k1 = INF; int i1 = 0x7fffffff;
        float k2 = INF; int i2 = 0x7fffffff;
#pragma unroll
        for (int c = 0; c < 4; c++) {
            float key = fmaf(-2.f, acc[r][c], qn[c]);
            int   j   = n0 + tx * 4 + c;
            if (lex_less(key, j, k1, i1)) { k2 = k1; i2 = i1; k1 = key; i1 = j; }
            else if (lex_less(key, j, k2, i2)) { k2 = key; i2 = j; }
        }
        // reduce across the 16 lanes (same ty) of the half-warp; xor<16 stays in group
#pragma unroll
        for (int o = 8; o; o >>= 1) {
            float ok1 = __shfl_xor_sync(0xffffffffu, k1, o);
            int   oi1 = __shfl_xor_sync(0xffffffffu, i1, o);
            float ok2 = __shfl_xor_sync(0xffffffffu, k2, o);
            int   oi2 = __shfl_xor_sync(0xffffffffu, i2, o);
            merge_top2(k1, i1, k2, i2, ok1, oi1, ok2, oi2);
        }
        if (tx == 0) {
            Top2 t; t.k1 = k1; t.i1 = i1; t.k2 = k2; t.i2 = i2;
            g_partial[(size_t)(m0 + ty * 4 + r) * NTILES + blockIdx.x] = t;
        }
    }
}

// ---------------------------------------------------------------------------
// Kernel 3: reduce 512 partials per row -> global top-2 -> nn = rank-1 index,
// then gather queue[nn] into the output row.
// ---------------------------------------------------------------------------
__global__ void __launch_bounds__(256) reduce_gather_kernel(const float* __restrict__ x,
                                                            const float* __restrict__ qp,
                                                            float* __restrict__ out) {
    const int row = blockIdx.x;
    const int tid = threadIdx.x;
    const float INF = __int_as_float(0x7f800000);

    float k1 = INF; int i1 = 0x7fffffff;
    float k2 = INF; int i2 = 0x7fffffff;

    const Top2* p = g_partial + (size_t)row * NTILES;
    for (int t = tid; t < NTILES; t += 256) {
        Top2 o = p[t];
        merge_top2(k1, i1, k2, i2, o.k1, o.i1, o.k2, o.i2);
    }

    __shared__ __align__(16) Top2 s[256];
    s[tid].k1 = k1; s[tid].i1 = i1; s[tid].k2 = k2; s[tid].i2 = i2;
    __syncthreads();
    for (int stride = 128; stride > 0; stride >>= 1) {
        if (tid < stride) {
            Top2 a = s[tid], b = s[tid + stride];
            merge_top2(a.k1, a.i1, a.k2, a.i2, b.k1, b.i1, b.k2, b.i2);
            s[tid] = a;
        }
        __syncthreads();
    }

    __shared__ int nn;
    if (tid == 0) nn = s[0].i2;   // rank-1 = second nearest (nearest is self)
    __syncthreads();

    const float4* src = (const float4*)queue_row(x, qp, nn);
    float4*       dst = (float4*)(out + (size_t)row * DIM);
    if (tid < DIM / 4) dst[tid] = src[tid];
}

// ---------------------------------------------------------------------------
extern "C" void kernel_launch(void* const* d_in, const int* in_sizes, int n_in,
                              void* d_out, int out_size) {
    const float* x  = (const float*)d_in[0];       // (1024, 512)
    const float* qp = (const float*)d_in[1];       // (32768, 512)
    float*       out = (float*)d_out;              // (1024, 512)

    qnorm_kernel<<<QSZ * 32 / 256, 256>>>(x, qp);

    dim3 grid(NTILES, BATCH / BM);                 // (512, 16)
    gemm_top2_kernel<<<grid, 256>>>(x, qp);

    reduce_gather_kernel<<<BATCH, 256>>>(x, qp, out);
}

// round 4
// speedup vs baseline: 3.1829x; 3.1829x over previous
#include <cuda_runtime.h>
#include <cuda_bf16.h>
#include <cstdint>

#define BATCH 1024
#define DIM   512
#define QSZ   32768
#define QOFF  (QSZ - BATCH)   // 31744

#define MT 128
#define NT 128
#define KC 32                 // k-chunk
#define NCHUNK (DIM / KC)     // 16
#define NTILES (QSZ / NT)     // 256 (CTA col tiles)
#define MTILES (BATCH / MT)   // 8
#define PT     (QSZ / 32)     // 1024 partial col-tiles (one per warp 32-col slab)

// ---------------------------------------------------------------------------
// helpers
// ---------------------------------------------------------------------------
__device__ __forceinline__ uint32_t smem_to_u32(const void* p) {
    uint32_t a;
    asm("{ .reg .u64 t; cvta.to.shared.u64 t, %1; cvt.u32.u64 %0, t; }" : "=r"(a) : "l"(p));
    return a;
}
__device__ __forceinline__ void cp16(uint32_t saddr, const void* g) {
    asm volatile("cp.async.cg.shared.global [%0], [%1], 16;" :: "r"(saddr), "l"(g));
}
#define CP_COMMIT() asm volatile("cp.async.commit_group;" ::: "memory")
#define CP_WAIT(N)  asm volatile("cp.async.wait_group %0;" :: "n"(N) : "memory")

__device__ __forceinline__ void ldm_x4(uint32_t (&r)[4], uint32_t addr) {
    asm volatile("ldmatrix.sync.aligned.m8n8.x4.shared.b16 {%0,%1,%2,%3}, [%4];"
                 : "=r"(r[0]), "=r"(r[1]), "=r"(r[2]), "=r"(r[3]) : "r"(addr));
}
__device__ __forceinline__ void mma16816(float (&c)[4], const uint32_t (&a)[4],
                                         uint32_t b0, uint32_t b1) {
    asm volatile("mma.sync.aligned.m16n8k16.row.col.f32.bf16.bf16.f32 "
                 "{%0,%1,%2,%3}, {%4,%5,%6,%7}, {%8,%9}, {%0,%1,%2,%3};"
                 : "+f"(c[0]), "+f"(c[1]), "+f"(c[2]), "+f"(c[3])
                 : "r"(a[0]), "r"(a[1]), "r"(a[2]), "r"(a[3]), "r"(b0), "r"(b1));
}

// swizzled smem byte offset inside a 128x32-bf16 tile (64B rows, 16B chunks)
__device__ __forceinline__ uint32_t swz(int row, int c8) {
    return (uint32_t)row * 64u + (uint32_t)((c8 ^ (row & 3)) * 16);
}

struct __align__(16) Top2 { float k1; int i1; float k2; int i2; };

__device__ __align__(16) __nv_bfloat16 g_qb[(size_t)QSZ * DIM];   // 32 MB bf16 queue
__device__ float g_qnorm[QSZ];
__device__ Top2  g_partial[(size_t)BATCH * PT];                   // 16 MB

__device__ __forceinline__ const float* queue_row(const float* x, const float* qp, int j) {
    return (j < QOFF) ? (qp + (size_t)(j + BATCH) * DIM)
                      : (x  + (size_t)(j - QOFF) * DIM);
}
__device__ __forceinline__ bool lex_less(float ak, int ai, float bk, int bi) {
    return ak < bk || (ak == bk && ai < bi);
}
__device__ __forceinline__ void merge2(float& k1, int& i1, float& k2, int& i2,
                                       float ok1, int oi1, float ok2, int oi2) {
    if (lex_less(ok1, oi1, k1, i1)) {
        if (lex_less(ok2, oi2, k1, i1)) { k2 = ok2; i2 = oi2; }
        else                            { k2 = k1;  i2 = i1;  }
        k1 = ok1; i1 = oi1;
    } else if (lex_less(ok1, oi1, k2, i2)) { k2 = ok1; i2 = oi1; }
}
__device__ __forceinline__ void insert4(float (&ks)[4], int (&is)[4], float k, int i) {
    if (!lex_less(k, i, ks[3], is[3])) return;
    int p = 3;
#pragma unroll
    for (int q = 3; q > 0; q--) {
        if (lex_less(k, i, ks[q-1], is[q-1])) { ks[q] = ks[q-1]; is[q] = is[q-1]; p = q-1; }
    }
    ks[p] = k; is[p] = i;
}

// ---------------------------------------------------------------------------
// Kernel 1: build bf16 queue + exact fp32 qnorm. 1 warp / row.
// ---------------------------------------------------------------------------
__global__ void __launch_bounds__(256) prep_kernel(const float* __restrict__ x,
                                                   const float* __restrict__ qp) {
    int w    = (blockIdx.x * blockDim.x + threadIdx.x) >> 5;
    int lane = threadIdx.x & 31;
    if (w >= QSZ) return;
    const float4* s4 = (const float4*)queue_row(x, qp, w);
    __nv_bfloat16* dst = g_qb + (size_t)w * DIM;
    float nrm = 0.f;
#pragma unroll
    for (int i = 0; i < 4; i++) {
        float4 v = s4[lane + 32 * i];
        nrm += v.x * v.x + v.y * v.y + v.z * v.z + v.w * v.w;
        __nv_bfloat162 p0 = __floats2bfloat162_rn(v.x, v.y);
        __nv_bfloat162 p1 = __floats2bfloat162_rn(v.z, v.w);
        uint2 pk = make_uint2(*(uint32_t*)&p0, *(uint32_t*)&p1);
        *(uint2*)(dst + (lane + 32 * i) * 4) = pk;
    }
#pragma unroll
    for (int o = 16; o; o >>= 1) nrm += __shfl_xor_sync(0xffffffffu, nrm, o);
    if (lane == 0) g_qnorm[w] = nrm;
}

// ---------------------------------------------------------------------------
// Kernel 2: mma.sync bf16 GEMM (128x128 tile, K=512) + fused per-row top-2.
// ---------------------------------------------------------------------------
__global__ void __launch_bounds__(256) mma_top2_kernel() {
    __shared__ __align__(16) char smA[2][8192];
    __shared__ __align__(16) char smB[2][8192];

    const int tid  = threadIdx.x;
    const int wid  = tid >> 5;
    const int lane = tid & 31;
    const int wm   = wid & 1;          // M half (64 rows)
    const int wn   = wid >> 1;         // N quarter (32 cols)
    const int m0   = blockIdx.y * MT;
    const int n0   = blockIdx.x * NT;

    const __nv_bfloat16* Ag = g_qb + (size_t)(QOFF + m0) * DIM;  // x rows at queue tail
    const __nv_bfloat16* Bg = g_qb + (size_t)n0 * DIM;

    const uint32_t sA[2] = { smem_to_u32(smA[0]), smem_to_u32(smA[1]) };
    const uint32_t sB[2] = { smem_to_u32(smB[0]), smem_to_u32(smB[1]) };

    // global->smem loader: 512 16B units per matrix, 2 per thread per matrix
    const int u0 = tid, u1 = tid + 256;
    const int r0g = u0 >> 2, c80 = u0 & 3;
    const int r1g = u1 >> 2, c81 = u1 & 3;
    const uint32_t so0 = swz(r0g, c80), so1 = swz(r1g, c81);

#define LOAD_CHUNK(ck, buf) do { \
    int koff = (ck) * KC; \
    cp16(sA[buf] + so0, Ag + (size_t)r0g * DIM + koff + c80 * 8); \
    cp16(sA[buf] + so1, Ag + (size_t)r1g * DIM + koff + c81 * 8); \
    cp16(sB[buf] + so0, Bg + (size_t)r0g * DIM + koff + c80 * 8); \
    cp16(sB[buf] + so1, Bg + (size_t)r1g * DIM + koff + c81 * 8); \
    CP_COMMIT(); \
} while (0)

    float acc[4][4][4] = {};

    LOAD_CHUNK(0, 0);
    for (int c = 0; c < NCHUNK; c++) {
        const int buf = c & 1;
        if (c + 1 < NCHUNK) { LOAD_CHUNK(c + 1, buf ^ 1); CP_WAIT(1); }
        else                { CP_WAIT(0); }
        __syncthreads();

#pragma unroll
        for (int ks = 0; ks < 2; ks++) {
            uint32_t af[4][4];
#pragma unroll
            for (int a = 0; a < 4; a++) {
                int row = wm * 64 + a * 16 + (lane & 15);
                int c8  = ks * 2 + (lane >> 4);
                ldm_x4(af[a], sA[buf] + swz(row, c8));
            }
            uint32_t bf[2][4];
#pragma unroll
            for (int b2 = 0; b2 < 2; b2++) {
                int g   = lane >> 3;
                int row = wn * 32 + b2 * 16 + (g >> 1) * 8 + (lane & 7);
                int c8  = ks * 2 + (g & 1);
                ldm_x4(bf[b2], sB[buf] + swz(row, c8));
            }
#pragma unroll
            for (int a = 0; a < 4; a++)
#pragma unroll
                for (int b = 0; b < 4; b++)
                    mma16816(acc[a][b], af[a], bf[b >> 1][(b & 1) * 2],
                                               bf[b >> 1][(b & 1) * 2 + 1]);
        }
        __syncthreads();
    }

    // Epilogue: keys = qnorm[j] - 2*S; per-row top-2 over this warp's 32 cols.
    const int gid = lane >> 2, tig = lane & 3;
    const float INF = __int_as_float(0x7f800000);

    float qn[4][2];
#pragma unroll
    for (int b = 0; b < 4; b++) {
        int j = n0 + wn * 32 + b * 8 + tig * 2;
        qn[b][0] = g_qnorm[j];
        qn[b][1] = g_qnorm[j + 1];
    }

    float k1[8], k2[8]; int i1[8], i2[8];
#pragma unroll
    for (int s = 0; s < 8; s++) { k1[s] = k2[s] = INF; i1[s] = i2[s] = 0x7fffffff; }

#pragma unroll
    for (int a = 0; a < 4; a++)
#pragma unroll
        for (int b = 0; b < 4; b++) {
            int j = n0 + wn * 32 + b * 8 + tig * 2;
#pragma unroll
            for (int h = 0; h < 2; h++) {       // h=0: row gid, h=1: row gid+8
                int s = a * 2 + h;
#pragma unroll
                for (int e = 0; e < 2; e++) {
                    float key = fmaf(-2.f, acc[a][b][h * 2 + e], qn[b][e]);
                    int   jj  = j + e;
                    if (lex_less(key, jj, k1[s], i1[s])) {
                        k2[s] = k1[s]; i2[s] = i1[s]; k1[s] = key; i1[s] = jj;
                    } else if (lex_less(key, jj, k2[s], i2[s])) { k2[s] = key; i2[s] = jj; }
                }
            }
        }

#pragma unroll
    for (int off = 1; off <= 2; off <<= 1) {
#pragma unroll
        for (int s = 0; s < 8; s++) {
            float ok1 = __shfl_xor_sync(0xffffffffu, k1[s], off);
            int   oi1 = __shfl_xor_sync(0xffffffffu, i1[s], off);
            float ok2 = __shfl_xor_sync(0xffffffffu, k2[s], off);
            int   oi2 = __shfl_xor_sync(0xffffffffu, i2[s], off);
            merge2(k1[s], i1[s], k2[s], i2[s], ok1, oi1, ok2, oi2);
        }
    }

    if (tig == 0) {
        int ct = blockIdx.x * 4 + wn;
#pragma unroll
        for (int s = 0; s < 8; s++) {
            int row = m0 + wm * 64 + (s >> 1) * 16 + (s & 1) * 8 + gid;
            Top2 t; t.k1 = k1[s]; t.i1 = i1[s]; t.k2 = k2[s]; t.i2 = i2[s];
            g_partial[(size_t)row * PT + ct] = t;
        }
    }
}

// ---------------------------------------------------------------------------
// Kernel 3: per-row reduce to approx top-4, exact fp32 rescore, pick 2nd
// smallest, gather the queue row. One warp per row.
// ---------------------------------------------------------------------------
__global__ void __launch_bounds__(256) reduce_rescore_kernel(const float* __restrict__ x,
                                                             const float* __restrict__ qp,
                                                             float* __restrict__ out) {
    const int gw   = (blockIdx.x * blockDim.x + threadIdx.x) >> 5;  // row
    const int lane = threadIdx.x & 31;
    if (gw >= BATCH) return;
    const float INF = __int_as_float(0x7f800000);

    float ks[4]; int is[4];
#pragma unroll
    for (int q = 0; q < 4; q++) { ks[q] = INF; is[q] = 0x7fffffff; }

    const Top2* p = g_partial + (size_t)gw * PT;
    for (int t = lane; t < PT; t += 32) {
        Top2 o = p[t];
        insert4(ks, is, o.k1, o.i1);
        insert4(ks, is, o.k2, o.i2);
    }
#pragma unroll
    for (int off = 16; off; off >>= 1) {
        float ok[4]; int oi[4];
#pragma unroll
        for (int q = 0; q < 4; q++) {
            ok[q] = __shfl_xor_sync(0xffffffffu, ks[q], off);
            oi[q] = __shfl_xor_sync(0xffffffffu, is[q], off);
        }
#pragma unroll
        for (int q = 0; q < 4; q++) insert4(ks, is, ok[q], oi[q]);
    }

    // exact fp32 rescore of the 4 candidates
    const float* xr = x + (size_t)gw * DIM;
    float ek[4];
#pragma unroll
    for (int cdx = 0; cdx < 4; cdx++) {
        const float* qr = queue_row(x, qp, is[cdx]);
        float s = 0.f;
#pragma unroll
        for (int kk = 0; kk < 4; kk++) {
            int k = (lane + 32 * kk) * 4;
            float4 a = *(const float4*)(xr + k);
            float4 b = *(const float4*)(qr + k);
            s += a.x * b.x + a.y * b.y + a.z * b.z + a.w * b.w;
        }
#pragma unroll
        for (int o = 16; o; o >>= 1) s += __shfl_xor_sync(0xffffffffu, s, o);
        ek[cdx] = g_qnorm[is[cdx]] - 2.f * s;
    }
    int best = 0;
#pragma unroll
    for (int c = 1; c < 4; c++) if (lex_less(ek[c], is[c], ek[best], is[best])) best = c;
    int sec = (best == 0) ? 1 : 0;
#pragma unroll
    for (int c = 0; c < 4; c++)
        if (c != best && lex_less(ek[c], is[c], ek[sec], is[sec])) sec = c;
    const int nn = is[sec];

    const float4* src = (const float4*)queue_row(x, qp, nn);
    float4*       dst = (float4*)(out + (size_t)gw * DIM);
#pragma unroll
    for (int kk = 0; kk < 4; kk++) dst[lane + 32 * kk] = src[lane + 32 * kk];
}

// ---------------------------------------------------------------------------
extern "C" void kernel_launch(void* const* d_in, const int* in_sizes, int n_in,
                              void* d_out, int out_size) {
    const float* x   = (const float*)d_in[0];   // (1024, 512)
    const float* qp  = (const float*)d_in[1];   // (32768, 512)
    float*       out = (float*)d_out;           // (1024, 512)

    prep_kernel<<<QSZ / 8, 256>>>(x, qp);

    dim3 grid(NTILES, MTILES);                  // (256, 8)
    mma_top2_kernel<<<grid, 256>>>();

    reduce_rescore_kernel<<<BATCH / 8, 256>>>(x, qp, out);
}

// round 5
// speedup vs baseline: 3.7321x; 1.1725x over previous
#include <cuda_runtime.h>
#include <cuda_bf16.h>
#include <cstdint>

#define BATCH 1024
#define DIM   512
#define QSZ   32768
#define QOFF  (QSZ - BATCH)   // 31744

#define MT 128
#define NT 256
#define KC 32                 // k-chunk
#define NCHUNK (DIM / KC)     // 16
#define NTILES (QSZ / NT)     // 128 CTA col tiles
#define MTILES (BATCH / MT)   // 8
#define PT     (QSZ / 64)     // 512 partial col slabs (one per warp 64-col slab)

#define NSTAGE 3
#define STG_A_BYTES 8192      // 128 x 32 bf16
#define STG_B_BYTES 16384     // 256 x 32 bf16
#define STG_BYTES   (STG_A_BYTES + STG_B_BYTES)
#define SMEM_BYTES  (NSTAGE * STG_BYTES)   // 73728

// ---------------------------------------------------------------------------
// helpers
// ---------------------------------------------------------------------------
__device__ __forceinline__ uint32_t smem_to_u32(const void* p) {
    uint32_t a;
    asm("{ .reg .u64 t; cvta.to.shared.u64 t, %1; cvt.u32.u64 %0, t; }" : "=r"(a) : "l"(p));
    return a;
}
__device__ __forceinline__ void cp16(uint32_t saddr, const void* g) {
    asm volatile("cp.async.cg.shared.global [%0], [%1], 16;" :: "r"(saddr), "l"(g));
}
#define CP_COMMIT() asm volatile("cp.async.commit_group;" ::: "memory")
#define CP_WAIT(N)  asm volatile("cp.async.wait_group %0;" :: "n"(N) : "memory")

__device__ __forceinline__ void ldm_x4(uint32_t (&r)[4], uint32_t addr) {
    asm volatile("ldmatrix.sync.aligned.m8n8.x4.shared.b16 {%0,%1,%2,%3}, [%4];"
                 : "=r"(r[0]), "=r"(r[1]), "=r"(r[2]), "=r"(r[3]) : "r"(addr));
}
__device__ __forceinline__ void mma16816(float (&c)[4], const uint32_t (&a)[4],
                                         uint32_t b0, uint32_t b1) {
    asm volatile("mma.sync.aligned.m16n8k16.row.col.f32.bf16.bf16.f32 "
                 "{%0,%1,%2,%3}, {%4,%5,%6,%7}, {%8,%9}, {%0,%1,%2,%3};"
                 : "+f"(c[0]), "+f"(c[1]), "+f"(c[2]), "+f"(c[3])
                 : "r"(a[0]), "r"(a[1]), "r"(a[2]), "r"(a[3]), "r"(b0), "r"(b1));
}

// swizzled smem byte offset inside a (rows x 32)-bf16 tile (64B rows, 16B chunks)
__device__ __forceinline__ uint32_t swz(int row, int c8) {
    return (uint32_t)row * 64u + (uint32_t)((c8 ^ (row & 3)) * 16);
}

struct __align__(16) Top2 { float k1; int i1; float k2; int i2; };

__device__ __align__(16) __nv_bfloat16 g_qb[(size_t)QSZ * DIM];   // 32 MB bf16 queue
__device__ float g_qnorm[QSZ];
__device__ Top2  g_partial[(size_t)BATCH * PT];                   // 8 MB

__device__ __forceinline__ const float* queue_row(const float* x, const float* qp, int j) {
    return (j < QOFF) ? (qp + (size_t)(j + BATCH) * DIM)
                      : (x  + (size_t)(j - QOFF) * DIM);
}
__device__ __forceinline__ bool lex_less(float ak, int ai, float bk, int bi) {
    return ak < bk || (ak == bk && ai < bi);
}
__device__ __forceinline__ void merge2(float& k1, int& i1, float& k2, int& i2,
                                       float ok1, int oi1, float ok2, int oi2) {
    if (lex_less(ok1, oi1, k1, i1)) {
        if (lex_less(ok2, oi2, k1, i1)) { k2 = ok2; i2 = oi2; }
        else                            { k2 = k1;  i2 = i1;  }
        k1 = ok1; i1 = oi1;
    } else if (lex_less(ok1, oi1, k2, i2)) { k2 = ok1; i2 = oi1; }
}
__device__ __forceinline__ void insert4(float (&ks)[4], int (&is)[4], float k, int i) {
    if (!lex_less(k, i, ks[3], is[3])) return;
    int p = 3;
#pragma unroll
    for (int q = 3; q > 0; q--) {
        if (lex_less(k, i, ks[q-1], is[q-1])) { ks[q] = ks[q-1]; is[q] = is[q-1]; p = q-1; }
    }
    ks[p] = k; is[p] = i;
}

// ---------------------------------------------------------------------------
// Kernel 1: build bf16 queue + exact fp32 qnorm. 1 warp / row.
// ---------------------------------------------------------------------------
__global__ void __launch_bounds__(256) prep_kernel(const float* __restrict__ x,
                                                   const float* __restrict__ qp) {
    int w    = (blockIdx.x * blockDim.x + threadIdx.x) >> 5;
    int lane = threadIdx.x & 31;
    if (w >= QSZ) return;
    const float4* s4 = (const float4*)queue_row(x, qp, w);
    __nv_bfloat16* dst = g_qb + (size_t)w * DIM;
    float nrm = 0.f;
#pragma unroll
    for (int i = 0; i < 4; i++) {
        float4 v = s4[lane + 32 * i];
        nrm += v.x * v.x + v.y * v.y + v.z * v.z + v.w * v.w;
        __nv_bfloat162 p0 = __floats2bfloat162_rn(v.x, v.y);
        __nv_bfloat162 p1 = __floats2bfloat162_rn(v.z, v.w);
        uint2 pk = make_uint2(*(uint32_t*)&p0, *(uint32_t*)&p1);
        *(uint2*)(dst + (lane + 32 * i) * 4) = pk;
    }
#pragma unroll
    for (int o = 16; o; o >>= 1) nrm += __shfl_xor_sync(0xffffffffu, nrm, o);
    if (lane == 0) g_qnorm[w] = nrm;
}

// ---------------------------------------------------------------------------
// Kernel 2: mma.sync bf16 GEMM, CTA tile 128x256, warp tile 64x64, K=512,
// 3-stage cp.async ring, fused per-row top-2 over 64-col slabs.
// ---------------------------------------------------------------------------
__global__ void __launch_bounds__(256, 1) mma_top2_kernel() {
    extern __shared__ __align__(16) char smem[];
    const uint32_t sbase = smem_to_u32(smem);

    const int tid  = threadIdx.x;
    const int wid  = tid >> 5;
    const int lane = tid & 31;
    const int wm   = wid & 1;          // M half (64 rows)
    const int wn   = wid >> 1;         // N quarter (64 cols)
    const int m0   = blockIdx.y * MT;
    const int n0   = blockIdx.x * NT;

    const __nv_bfloat16* Ag = g_qb + (size_t)(QOFF + m0) * DIM;  // x rows at queue tail
    const __nv_bfloat16* Bg = g_qb + (size_t)n0 * DIM;

    // loaders: A 512 16B-units (2/thread), B 1024 units (4/thread)
    const int rA0 = tid >> 2,          cA0 = tid & 3;
    const int rA1 = (tid + 256) >> 2,  cA1 = tid & 3;
    const uint32_t soA0 = swz(rA0, cA0), soA1 = swz(rA1, cA1);
    uint32_t soB[4]; int rB[4];
#pragma unroll
    for (int u = 0; u < 4; u++) {
        int uu = tid + 256 * u;
        rB[u] = uu >> 2;
        soB[u] = swz(rB[u], uu & 3);
    }
    const int cB = tid & 3;

#define LOAD_CHUNK(ck, stg) do { \
    uint32_t _sA = sbase + (uint32_t)(stg) * STG_BYTES; \
    uint32_t _sB = _sA + STG_A_BYTES; \
    int _ko = (ck) * KC; \
    cp16(_sA + soA0, Ag + (size_t)rA0 * DIM + _ko + cA0 * 8); \
    cp16(_sA + soA1, Ag + (size_t)rA1 * DIM + _ko + cA1 * 8); \
    cp16(_sB + soB[0], Bg + (size_t)rB[0] * DIM + _ko + cB * 8); \
    cp16(_sB + soB[1], Bg + (size_t)rB[1] * DIM + _ko + cB * 8); \
    cp16(_sB + soB[2], Bg + (size_t)rB[2] * DIM + _ko + cB * 8); \
    cp16(_sB + soB[3], Bg + (size_t)rB[3] * DIM + _ko + cB * 8); \
    CP_COMMIT(); \
} while (0)

    float acc[4][8][4] = {};

    LOAD_CHUNK(0, 0);
    LOAD_CHUNK(1, 1);

    for (int c = 0; c < NCHUNK; c++) {
        const int stg = c % NSTAGE;
        CP_WAIT(1);
        __syncthreads();
        if (c + 2 < NCHUNK) LOAD_CHUNK(c + 2, (c + 2) % NSTAGE);

        const uint32_t sA = sbase + (uint32_t)stg * STG_BYTES;
        const uint32_t sB = sA + STG_A_BYTES;

#pragma unroll
        for (int ks = 0; ks < 2; ks++) {
            uint32_t af[4][4];
#pragma unroll
            for (int a = 0; a < 4; a++) {
                int row = wm * 64 + a * 16 + (lane & 15);
                int c8  = ks * 2 + (lane >> 4);
                ldm_x4(af[a], sA + swz(row, c8));
            }
            uint32_t bf[4][4];
#pragma unroll
            for (int b2 = 0; b2 < 4; b2++) {
                int g   = lane >> 3;
                int row = wn * 64 + b2 * 16 + (g >> 1) * 8 + (lane & 7);
                int c8  = ks * 2 + (g & 1);
                ldm_x4(bf[b2], sB + swz(row, c8));
            }
#pragma unroll
            for (int a = 0; a < 4; a++)
#pragma unroll
                for (int b = 0; b < 8; b++)
                    mma16816(acc[a][b], af[a], bf[b >> 1][(b & 1) * 2],
                                               bf[b >> 1][(b & 1) * 2 + 1]);
        }
    }

    // Epilogue: keys = qnorm[j] - 2*S; per-row top-2 over this warp's 64 cols.
    const int gid = lane >> 2, tig = lane & 3;
    const float INF = __int_as_float(0x7f800000);

    float qn[8][2];
#pragma unroll
    for (int b = 0; b < 8; b++) {
        int j = n0 + wn * 64 + b * 8 + tig * 2;
        qn[b][0] = g_qnorm[j];
        qn[b][1] = g_qnorm[j + 1];
    }

    float k1[8], k2[8]; int i1[8], i2[8];
#pragma unroll
    for (int s = 0; s < 8; s++) { k1[s] = k2[s] = INF; i1[s] = i2[s] = 0x7fffffff; }

#pragma unroll
    for (int a = 0; a < 4; a++)
#pragma unroll
        for (int b = 0; b < 8; b++) {
            int j = n0 + wn * 64 + b * 8 + tig * 2;
#pragma unroll
            for (int h = 0; h < 2; h++) {       // h=0: row gid, h=1: row gid+8
                int s = a * 2 + h;
#pragma unroll
                for (int e = 0; e < 2; e++) {
                    float key = fmaf(-2.f, acc[a][b][h * 2 + e], qn[b][e]);
                    int   jj  = j + e;
                    if (lex_less(key, jj, k1[s], i1[s])) {
                        k2[s] = k1[s]; i2[s] = i1[s]; k1[s] = key; i1[s] = jj;
                    } else if (lex_less(key, jj, k2[s], i2[s])) { k2[s] = key; i2[s] = jj; }
                }
            }
        }

#pragma unroll
    for (int off = 1; off <= 2; off <<= 1) {
#pragma unroll
        for (int s = 0; s < 8; s++) {
            float ok1 = __shfl_xor_sync(0xffffffffu, k1[s], off);
            int   oi1 = __shfl_xor_sync(0xffffffffu, i1[s], off);
            float ok2 = __shfl_xor_sync(0xffffffffu, k2[s], off);
            int   oi2 = __shfl_xor_sync(0xffffffffu, i2[s], off);
            merge2(k1[s], i1[s], k2[s], i2[s], ok1, oi1, ok2, oi2);
        }
    }

    if (tig == 0) {
        int ct = blockIdx.x * 4 + wn;
#pragma unroll
        for (int s = 0; s < 8; s++) {
            int row = m0 + wm * 64 + (s >> 1) * 16 + (s & 1) * 8 + gid;
            Top2 t; t.k1 = k1[s]; t.i1 = i1[s]; t.k2 = k2[s]; t.i2 = i2[s];
            g_partial[(size_t)row * PT + ct] = t;
        }
    }
}

// ---------------------------------------------------------------------------
// Kernel 3: per-row reduce to approx top-4, exact fp32 rescore, pick 2nd
// smallest, gather the queue row. One warp per row.
// ---------------------------------------------------------------------------
__global__ void __launch_bounds__(256) reduce_rescore_kernel(const float* __restrict__ x,
                                                             const float* __restrict__ qp,
                                                             float* __restrict__ out) {
    const int gw   = (blockIdx.x * blockDim.x + threadIdx.x) >> 5;  // row
    const int lane = threadIdx.x & 31;
    if (gw >= BATCH) return;
    const float INF = __int_as_float(0x7f800000);

    float ks[4]; int is[4];
#pragma unroll
    for (int q = 0; q < 4; q++) { ks[q] = INF; is[q] = 0x7fffffff; }

    const Top2* p = g_partial + (size_t)gw * PT;
    for (int t = lane; t < PT; t += 32) {
        Top2 o = p[t];
        insert4(ks, is, o.k1, o.i1);
        insert4(ks, is, o.k2, o.i2);
    }
#pragma unroll
    for (int off = 16; off; off >>= 1) {
        float ok[4]; int oi[4];
#pragma unroll
        for (int q = 0; q < 4; q++) {
            ok[q] = __shfl_xor_sync(0xffffffffu, ks[q], off);
            oi[q] = __shfl_xor_sync(0xffffffffu, is[q], off);
        }
#pragma unroll
        for (int q = 0; q < 4; q++) insert4(ks, is, ok[q], oi[q]);
    }

    // exact fp32 rescore of the 4 candidates
    const float* xr = x + (size_t)gw * DIM;
    float ek[4];
#pragma unroll
    for (int cdx = 0; cdx < 4; cdx++) {
        const float* qr = queue_row(x, qp, is[cdx]);
        float s = 0.f;
#pragma unroll
        for (int kk = 0; kk < 4; kk++) {
            int k = (lane + 32 * kk) * 4;
            float4 a = *(const float4*)(xr + k);
            float4 b = *(const float4*)(qr + k);
            s += a.x * b.x + a.y * b.y + a.z * b.z + a.w * b.w;
        }
#pragma unroll
        for (int o = 16; o; o >>= 1) s += __shfl_xor_sync(0xffffffffu, s, o);
        ek[cdx] = g_qnorm[is[cdx]] - 2.f * s;
    }
    int best = 0;
#pragma unroll
    for (int c = 1; c < 4; c++) if (lex_less(ek[c], is[c], ek[best], is[best])) best = c;
    int sec = (best == 0) ? 1 : 0;
#pragma unroll
    for (int c = 0; c < 4; c++)
        if (c != best && lex_less(ek[c], is[c], ek[sec], is[sec])) sec = c;
    const int nn = is[sec];

    const float4* src = (const float4*)queue_row(x, qp, nn);
    float4*       dst = (float4*)(out + (size_t)gw * DIM);
#pragma unroll
    for (int kk = 0; kk < 4; kk++) dst[lane + 32 * kk] = src[lane + 32 * kk];
}

// ---------------------------------------------------------------------------
extern "C" void kernel_launch(void* const* d_in, const int* in_sizes, int n_in,
                              void* d_out, int out_size) {
    const float* x   = (const float*)d_in[0];   // (1024, 512)
    const float* qp  = (const float*)d_in[1];   // (32768, 512)
    float*       out = (float*)d_out;           // (1024, 512)

    cudaFuncSetAttribute(mma_top2_kernel,
                         cudaFuncAttributeMaxDynamicSharedMemorySize, SMEM_BYTES);

    prep_kernel<<<QSZ / 8, 256>>>(x, qp);

    dim3 grid(NTILES, MTILES);                  // (128, 8)
    mma_top2_kernel<<<grid, 256, SMEM_BYTES>>>();

    reduce_rescore_kernel<<<BATCH / 8, 256>>>(x, qp, out);
}

// round 6
// speedup vs baseline: 4.1747x; 1.1186x over previous
#include <cuda_runtime.h>
#include <cuda_bf16.h>
#include <cstdint>

#define BATCH 1024
#define DIM   512
#define QSZ   32768
#define QOFF  (QSZ - BATCH)   // 31744

#define MT 128
#define NT 256
#define KC 64                 // k-chunk
#define NCHUNK (DIM / KC)     // 8
#define NTILES (QSZ / NT)     // 128 CTA col tiles
#define MTILES (BATCH / MT)   // 8
#define PT     (QSZ / 64)     // 512 partial col slabs (one per warp 64-col slab)

#define NSTAGE 3
#define STG_A_BYTES (128 * KC * 2)   // 16384
#define STG_B_BYTES (256 * KC * 2)   // 32768
#define STG_BYTES   (STG_A_BYTES + STG_B_BYTES)   // 49152
#define SMEM_BYTES  (NSTAGE * STG_BYTES)          // 147456

// ---------------------------------------------------------------------------
// helpers
// ---------------------------------------------------------------------------
__device__ __forceinline__ uint32_t smem_to_u32(const void* p) {
    uint32_t a;
    asm("{ .reg .u64 t; cvta.to.shared.u64 t, %1; cvt.u32.u64 %0, t; }" : "=r"(a) : "l"(p));
    return a;
}
__device__ __forceinline__ void cp16(uint32_t saddr, const void* g) {
    asm volatile("cp.async.cg.shared.global [%0], [%1], 16;" :: "r"(saddr), "l"(g));
}
#define CP_COMMIT() asm volatile("cp.async.commit_group;" ::: "memory")
#define CP_WAIT(N)  asm volatile("cp.async.wait_group %0;" :: "n"(N) : "memory")

__device__ __forceinline__ void ldm_x4(uint32_t (&r)[4], uint32_t addr) {
    asm volatile("ldmatrix.sync.aligned.m8n8.x4.shared.b16 {%0,%1,%2,%3}, [%4];"
                 : "=r"(r[0]), "=r"(r[1]), "=r"(r[2]), "=r"(r[3]) : "r"(addr));
}
__device__ __forceinline__ void mma16816(float (&c)[4], const uint32_t (&a)[4],
                                         uint32_t b0, uint32_t b1) {
    asm volatile("mma.sync.aligned.m16n8k16.row.col.f32.bf16.bf16.f32 "
                 "{%0,%1,%2,%3}, {%4,%5,%6,%7}, {%8,%9}, {%0,%1,%2,%3};"
                 : "+f"(c[0]), "+f"(c[1]), "+f"(c[2]), "+f"(c[3])
                 : "r"(a[0]), "r"(a[1]), "r"(a[2]), "r"(a[3]), "r"(b0), "r"(b1));
}

// swizzled smem byte offset inside a (rows x 64)-bf16 tile (128B rows, 16B chunks)
__device__ __forceinline__ uint32_t swz128(int row, int c8) {
    return (uint32_t)row * 128u + (uint32_t)(((c8) ^ (row & 7)) * 16);
}

struct __align__(16) Top2 { float k1; int i1; float k2; int i2; };

__device__ __align__(16) __nv_bfloat16 g_qb[(size_t)QSZ * DIM];   // 32 MB bf16 queue
__device__ float g_qnorm[QSZ];
__device__ Top2  g_partial[(size_t)BATCH * PT];                   // 8 MB

__device__ __forceinline__ const float* queue_row(const float* x, const float* qp, int j) {
    return (j < QOFF) ? (qp + (size_t)(j + BATCH) * DIM)
                      : (x  + (size_t)(j - QOFF) * DIM);
}
__device__ __forceinline__ bool lex_less(float ak, int ai, float bk, int bi) {
    return ak < bk || (ak == bk && ai < bi);
}
__device__ __forceinline__ void merge2(float& k1, int& i1, float& k2, int& i2,
                                       float ok1, int oi1, float ok2, int oi2) {
    if (lex_less(ok1, oi1, k1, i1)) {
        if (lex_less(ok2, oi2, k1, i1)) { k2 = ok2; i2 = oi2; }
        else                            { k2 = k1;  i2 = i1;  }
        k1 = ok1; i1 = oi1;
    } else if (lex_less(ok1, oi1, k2, i2)) { k2 = ok1; i2 = oi1; }
}
__device__ __forceinline__ void insert4(float (&ks)[4], int (&is)[4], float k, int i) {
    if (!lex_less(k, i, ks[3], is[3])) return;
    int p = 3;
#pragma unroll
    for (int q = 3; q > 0; q--) {
        if (lex_less(k, i, ks[q-1], is[q-1])) { ks[q] = ks[q-1]; is[q] = is[q-1]; p = q-1; }
    }
    ks[p] = k; is[p] = i;
}

// ---------------------------------------------------------------------------
// Kernel 1: build bf16 queue + exact fp32 qnorm. 1 warp / row.
// ---------------------------------------------------------------------------
__global__ void __launch_bounds__(256) prep_kernel(const float* __restrict__ x,
                                                   const float* __restrict__ qp) {
    int w    = (blockIdx.x * blockDim.x + threadIdx.x) >> 5;
    int lane = threadIdx.x & 31;
    if (w >= QSZ) return;
    const float4* s4 = (const float4*)queue_row(x, qp, w);
    __nv_bfloat16* dst = g_qb + (size_t)w * DIM;
    float nrm = 0.f;
#pragma unroll
    for (int i = 0; i < 4; i++) {
        float4 v = s4[lane + 32 * i];
        nrm += v.x * v.x + v.y * v.y + v.z * v.z + v.w * v.w;
        __nv_bfloat162 p0 = __floats2bfloat162_rn(v.x, v.y);
        __nv_bfloat162 p1 = __floats2bfloat162_rn(v.z, v.w);
        uint2 pk = make_uint2(*(uint32_t*)&p0, *(uint32_t*)&p1);
        *(uint2*)(dst + (lane + 32 * i) * 4) = pk;
    }
#pragma unroll
    for (int o = 16; o; o >>= 1) nrm += __shfl_xor_sync(0xffffffffu, nrm, o);
    if (lane == 0) g_qnorm[w] = nrm;
}

// ---------------------------------------------------------------------------
// Kernel 2: mma.sync bf16 GEMM, CTA tile 128x256, warp tile 64x64, K=512,
// KC=64 chunks, 3-stage cp.async ring, register-double-buffered fragments,
// fused per-row top-2 over 64-col slabs.
// ---------------------------------------------------------------------------
__global__ void __launch_bounds__(256, 1) mma_top2_kernel() {
    extern __shared__ __align__(16) char smem[];
    const uint32_t sbase = smem_to_u32(smem);

    const int tid  = threadIdx.x;
    const int wid  = tid >> 5;
    const int lane = tid & 31;
    const int wm   = wid & 1;          // M half (64 rows)
    const int wn   = wid >> 1;         // N quarter (64 cols)
    const int m0   = blockIdx.y * MT;
    const int n0   = blockIdx.x * NT;

    const __nv_bfloat16* Ag = g_qb + (size_t)(QOFF + m0) * DIM;  // x rows at queue tail
    const __nv_bfloat16* Bg = g_qb + (size_t)n0 * DIM;

    // loaders: A 1024 16B-units (4/thread), B 2048 units (8/thread)
    int rA[4]; uint32_t soA[4]; int c8A[4];
#pragma unroll
    for (int u = 0; u < 4; u++) {
        int uu = tid + 256 * u;
        rA[u] = uu >> 3; c8A[u] = uu & 7; soA[u] = swz128(rA[u], c8A[u]);
    }
    int rB[8]; uint32_t soB[8]; int c8B[8];
#pragma unroll
    for (int u = 0; u < 8; u++) {
        int uu = tid + 256 * u;
        rB[u] = uu >> 3; c8B[u] = uu & 7; soB[u] = swz128(rB[u], c8B[u]);
    }

#define LOAD_CHUNK(ck, stg) do { \
    uint32_t _sA = sbase + (uint32_t)(stg) * STG_BYTES; \
    uint32_t _sB = _sA + STG_A_BYTES; \
    int _ko = (ck) * KC; \
    _Pragma("unroll") \
    for (int _u = 0; _u < 4; _u++) \
        cp16(_sA + soA[_u], Ag + (size_t)rA[_u] * DIM + _ko + c8A[_u] * 8); \
    _Pragma("unroll") \
    for (int _u = 0; _u < 8; _u++) \
        cp16(_sB + soB[_u], Bg + (size_t)rB[_u] * DIM + _ko + c8B[_u] * 8); \
    CP_COMMIT(); \
} while (0)

    // fragment loads for k-step ks (0..3) from stage base
    const int arow_lo = wm * 64 + (lane & 15);
    const int ac8_lo  = (lane >> 4);
    const int bg      = lane >> 3;
    const int brow_lo = wn * 64 + (bg >> 1) * 8 + (lane & 7);
    const int bc8_lo  = (bg & 1);

#define LOAD_FRAGS(ks, sA, sB, af, bf) do { \
    _Pragma("unroll") \
    for (int _a = 0; _a < 4; _a++) \
        ldm_x4(af[_a], (sA) + swz128(arow_lo + _a * 16, (ks) * 2 + ac8_lo)); \
    _Pragma("unroll") \
    for (int _b = 0; _b < 4; _b++) \
        ldm_x4(bf[_b], (sB) + swz128(brow_lo + _b * 16, (ks) * 2 + bc8_lo)); \
} while (0)

    float acc[4][8][4] = {};
    uint32_t af[2][4][4], bf[2][4][4];

    LOAD_CHUNK(0, 0);
    LOAD_CHUNK(1, 1);

    for (int c = 0; c < NCHUNK; c++) {
        const int stg = c % NSTAGE;
        CP_WAIT(1);
        __syncthreads();
        if (c + 2 < NCHUNK) LOAD_CHUNK(c + 2, (c + 2) % NSTAGE);

        const uint32_t sA = sbase + (uint32_t)stg * STG_BYTES;
        const uint32_t sB = sA + STG_A_BYTES;

        LOAD_FRAGS(0, sA, sB, af[0], bf[0]);
#pragma unroll
        for (int ks = 0; ks < 4; ks++) {
            if (ks < 3) LOAD_FRAGS(ks + 1, sA, sB, af[(ks + 1) & 1], bf[(ks + 1) & 1]);
            const int cur = ks & 1;
#pragma unroll
            for (int a = 0; a < 4; a++)
#pragma unroll
                for (int b = 0; b < 8; b++)
                    mma16816(acc[a][b], af[cur][a], bf[cur][b >> 1][(b & 1) * 2],
                                                    bf[cur][b >> 1][(b & 1) * 2 + 1]);
        }
    }

    // Epilogue: keys = qnorm[j] - 2*S; per-row top-2 over this warp's 64 cols.
    const int gid = lane >> 2, tig = lane & 3;
    const float INF = __int_as_float(0x7f800000);

    float qn[8][2];
#pragma unroll
    for (int b = 0; b < 8; b++) {
        int j = n0 + wn * 64 + b * 8 + tig * 2;
        qn[b][0] = g_qnorm[j];
        qn[b][1] = g_qnorm[j + 1];
    }

    float k1[8], k2[8]; int i1[8], i2[8];
#pragma unroll
    for (int s = 0; s < 8; s++) { k1[s] = k2[s] = INF; i1[s] = i2[s] = 0x7fffffff; }

#pragma unroll
    for (int a = 0; a < 4; a++)
#pragma unroll
        for (int b = 0; b < 8; b++) {
            int j = n0 + wn * 64 + b * 8 + tig * 2;
#pragma unroll
            for (int h = 0; h < 2; h++) {       // h=0: row gid, h=1: row gid+8
                int s = a * 2 + h;
#pragma unroll
                for (int e = 0; e < 2; e++) {
                    float key = fmaf(-2.f, acc[a][b][h * 2 + e], qn[b][e]);
                    int   jj  = j + e;
                    if (lex_less(key, jj, k1[s], i1[s])) {
                        k2[s] = k1[s]; i2[s] = i1[s]; k1[s] = key; i1[s] = jj;
                    } else if (lex_less(key, jj, k2[s], i2[s])) { k2[s] = key; i2[s] = jj; }
                }
            }
        }

#pragma unroll
    for (int off = 1; off <= 2; off <<= 1) {
#pragma unroll
        for (int s = 0; s < 8; s++) {
            float ok1 = __shfl_xor_sync(0xffffffffu, k1[s], off);
            int   oi1 = __shfl_xor_sync(0xffffffffu, i1[s], off);
            float ok2 = __shfl_xor_sync(0xffffffffu, k2[s], off);
            int   oi2 = __shfl_xor_sync(0xffffffffu, i2[s], off);
            merge2(k1[s], i1[s], k2[s], i2[s], ok1, oi1, ok2, oi2);
        }
    }

    if (tig == 0) {
        int ct = blockIdx.x * 4 + wn;
#pragma unroll
        for (int s = 0; s < 8; s++) {
            int row = m0 + wm * 64 + (s >> 1) * 16 + (s & 1) * 8 + gid;
            Top2 t; t.k1 = k1[s]; t.i1 = i1[s]; t.k2 = k2[s]; t.i2 = i2[s];
            g_partial[(size_t)row * PT + ct] = t;
        }
    }
}

// ---------------------------------------------------------------------------
// Kernel 3: per-row reduce to approx top-4, exact fp32 rescore, pick 2nd
// smallest, gather the queue row. One warp per row.
// ---------------------------------------------------------------------------
__global__ void __launch_bounds__(256) reduce_rescore_kernel(const float* __restrict__ x,
                                                             const float* __restrict__ qp,
                                                             float* __restrict__ out) {
    const int gw   = (blockIdx.x * blockDim.x + threadIdx.x) >> 5;  // row
    const int lane = threadIdx.x & 31;
    if (gw >= BATCH) return;
    const float INF = __int_as_float(0x7f800000);

    float ks[4]; int is[4];
#pragma unroll
    for (int q = 0; q < 4; q++) { ks[q] = INF; is[q] = 0x7fffffff; }

    const Top2* p = g_partial + (size_t)gw * PT;
    for (int t = lane; t < PT; t += 32) {
        Top2 o = p[t];
        insert4(ks, is, o.k1, o.i1);
        insert4(ks, is, o.k2, o.i2);
    }
#pragma unroll
    for (int off = 16; off; off >>= 1) {
        float ok[4]; int oi[4];
#pragma unroll
        for (int q = 0; q < 4; q++) {
            ok[q] = __shfl_xor_sync(0xffffffffu, ks[q], off);
            oi[q] = __shfl_xor_sync(0xffffffffu, is[q], off);
        }
#pragma unroll
        for (int q = 0; q < 4; q++) insert4(ks, is, ok[q], oi[q]);
    }

    // exact fp32 rescore of the 4 candidates
    const float* xr = x + (size_t)gw * DIM;
    float ek[4];
#pragma unroll
    for (int cdx = 0; cdx < 4; cdx++) {
        const float* qr = queue_row(x, qp, is[cdx]);
        float s = 0.f;
#pragma unroll
        for (int kk = 0; kk < 4; kk++) {
            int k = (lane + 32 * kk) * 4;
            float4 a = *(const float4*)(xr + k);
            float4 b = *(const float4*)(qr + k);
            s += a.x * b.x + a.y * b.y + a.z * b.z + a.w * b.w;
        }
#pragma unroll
        for (int o = 16; o; o >>= 1) s += __shfl_xor_sync(0xffffffffu, s, o);
        ek[cdx] = g_qnorm[is[cdx]] - 2.f * s;
    }
    int best = 0;
#pragma unroll
    for (int c = 1; c < 4; c++) if (lex_less(ek[c], is[c], ek[best], is[best])) best = c;
    int sec = (best == 0) ? 1 : 0;
#pragma unroll
    for (int c = 0; c < 4; c++)
        if (c != best && lex_less(ek[c], is[c], ek[sec], is[sec])) sec = c;
    const int nn = is[sec];

    const float4* src = (const float4*)queue_row(x, qp, nn);
    float4*       dst = (float4*)(out + (size_t)gw * DIM);
#pragma unroll
    for (int kk = 0; kk < 4; kk++) dst[lane + 32 * kk] = src[lane + 32 * kk];
}

// ---------------------------------------------------------------------------
extern "C" void kernel_launch(void* const* d_in, const int* in_sizes, int n_in,
                              void* d_out, int out_size) {
    const float* x   = (const float*)d_in[0];   // (1024, 512)
    const float* qp  = (const float*)d_in[1];   // (32768, 512)
    float*       out = (float*)d_out;           // (1024, 512)

    cudaFuncSetAttribute(mma_top2_kernel,
                         cudaFuncAttributeMaxDynamicSharedMemorySize, SMEM_BYTES);

    prep_kernel<<<QSZ / 8, 256>>>(x, qp);

    dim3 grid(NTILES, MTILES);                  // (128, 8)
    mma_top2_kernel<<<grid, 256, SMEM_BYTES>>>();

    reduce_rescore_kernel<<<BATCH / 8, 256>>>(x, qp, out);
}

// round 7
// speedup vs baseline: 5.7206x; 1.3703x over previous
#include <cuda_runtime.h>
#include <cuda_fp16.h>
#include <cstdint>

#define BATCH 1024
#define DIM   512
#define QSZ   32768
#define QOFF  (QSZ - BATCH)   // 31744

#define MT 128
#define NT 256
#define KC 64                 // k-chunk
#define NCHUNK (DIM / KC)     // 8
#define NTILES (QSZ / NT)     // 128 CTA col tiles
#define MTILES (BATCH / MT)   // 8
#define PT     (QSZ / 64)     // 512 partial col slabs (one per warp 64-col slab)

#define NSTAGE 2
#define STG_A_BYTES (128 * KC * 2)   // 16384
#define STG_B_BYTES (256 * KC * 2)   // 32768
#define STG_BYTES   (STG_A_BYTES + STG_B_BYTES)   // 49152
#define SMEM_BYTES  (NSTAGE * STG_BYTES)          // 98304

// ---------------------------------------------------------------------------
// helpers
// ---------------------------------------------------------------------------
__device__ __forceinline__ uint32_t smem_to_u32(const void* p) {
    uint32_t a;
    asm("{ .reg .u64 t; cvta.to.shared.u64 t, %1; cvt.u32.u64 %0, t; }" : "=r"(a) : "l"(p));
    return a;
}
__device__ __forceinline__ void cp16(uint32_t saddr, const void* g) {
    asm volatile("cp.async.cg.shared.global [%0], [%1], 16;" :: "r"(saddr), "l"(g));
}
#define CP_COMMIT() asm volatile("cp.async.commit_group;" ::: "memory")
#define CP_WAIT(N)  asm volatile("cp.async.wait_group %0;" :: "n"(N) : "memory")

__device__ __forceinline__ void ldm_x4(uint32_t (&r)[4], uint32_t addr) {
    asm volatile("ldmatrix.sync.aligned.m8n8.x4.shared.b16 {%0,%1,%2,%3}, [%4];"
                 : "=r"(r[0]), "=r"(r[1]), "=r"(r[2]), "=r"(r[3]) : "r"(addr));
}
// m16n8k16, fp16 inputs, fp16 accumulate (C/D = 2 x f16x2 regs)
__device__ __forceinline__ void mma16816h(uint32_t (&c)[2], const uint32_t (&a)[4],
                                          uint32_t b0, uint32_t b1) {
    asm volatile("mma.sync.aligned.m16n8k16.row.col.f16.f16.f16.f16 "
                 "{%0,%1}, {%2,%3,%4,%5}, {%6,%7}, {%0,%1};"
                 : "+r"(c[0]), "+r"(c[1])
                 : "r"(a[0]), "r"(a[1]), "r"(a[2]), "r"(a[3]), "r"(b0), "r"(b1));
}

// swizzled smem byte offset inside a (rows x 64)-fp16 tile (128B rows, 16B chunks)
__device__ __forceinline__ uint32_t swz128(int row, int c8) {
    return (uint32_t)row * 128u + (uint32_t)(((c8) ^ (row & 7)) * 16);
}

struct __align__(16) Top2 { float k1; int i1; float k2; int i2; };

__device__ __align__(16) __half g_qh[(size_t)QSZ * DIM];          // 32 MB fp16 queue
__device__ float g_qnorm[QSZ];
__device__ Top2  g_partial[(size_t)BATCH * PT];                   // 8 MB

__device__ __forceinline__ const float* queue_row(const float* x, const float* qp, int j) {
    return (j < QOFF) ? (qp + (size_t)(j + BATCH) * DIM)
                      : (x  + (size_t)(j - QOFF) * DIM);
}
__device__ __forceinline__ bool lex_less(float ak, int ai, float bk, int bi) {
    return ak < bk || (ak == bk && ai < bi);
}
__device__ __forceinline__ void merge2(float& k1, int& i1, float& k2, int& i2,
                                       float ok1, int oi1, float ok2, int oi2) {
    if (lex_less(ok1, oi1, k1, i1)) {
        if (lex_less(ok2, oi2, k1, i1)) { k2 = ok2; i2 = oi2; }
        else                            { k2 = k1;  i2 = i1;  }
        k1 = ok1; i1 = oi1;
    } else if (lex_less(ok1, oi1, k2, i2)) { k2 = ok1; i2 = oi1; }
}
__device__ __forceinline__ void insert4(float (&ks)[4], int (&is)[4], float k, int i) {
    if (!lex_less(k, i, ks[3], is[3])) return;
    int p = 3;
#pragma unroll
    for (int q = 3; q > 0; q--) {
        if (lex_less(k, i, ks[q-1], is[q-1])) { ks[q] = ks[q-1]; is[q] = is[q-1]; p = q-1; }
    }
    ks[p] = k; is[p] = i;
}

// ---------------------------------------------------------------------------
// Kernel 1: build fp16 queue + exact fp32 qnorm. 1 warp / row.
// ---------------------------------------------------------------------------
__global__ void __launch_bounds__(256) prep_kernel(const float* __restrict__ x,
                                                   const float* __restrict__ qp) {
    int w    = (blockIdx.x * blockDim.x + threadIdx.x) >> 5;
    int lane = threadIdx.x & 31;
    if (w >= QSZ) return;
    const float4* s4 = (const float4*)queue_row(x, qp, w);
    __half* dst = g_qh + (size_t)w * DIM;
    float nrm = 0.f;
#pragma unroll
    for (int i = 0; i < 4; i++) {
        float4 v = s4[lane + 32 * i];
        nrm += v.x * v.x + v.y * v.y + v.z * v.z + v.w * v.w;
        __half2 p0 = __floats2half2_rn(v.x, v.y);
        __half2 p1 = __floats2half2_rn(v.z, v.w);
        uint2 pk = make_uint2(*(uint32_t*)&p0, *(uint32_t*)&p1);
        *(uint2*)(dst + (lane + 32 * i) * 4) = pk;
    }
#pragma unroll
    for (int o = 16; o; o >>= 1) nrm += __shfl_xor_sync(0xffffffffu, nrm, o);
    if (lane == 0) g_qnorm[w] = nrm;
}

// ---------------------------------------------------------------------------
// Kernel 2: mma.sync fp16 GEMM (fp16 accumulate), CTA tile 128x256, warp tile
// 64x64, KC=64, 2-stage cp.async ring, 2 CTAs/SM, fused per-row top-2.
// ---------------------------------------------------------------------------
__global__ void __launch_bounds__(256, 2) mma_top2_kernel() {
    extern __shared__ __align__(16) char smem[];
    const uint32_t sbase = smem_to_u32(smem);

    const int tid  = threadIdx.x;
    const int wid  = tid >> 5;
    const int lane = tid & 31;
    const int wm   = wid & 1;          // M half (64 rows)
    const int wn   = wid >> 1;         // N quarter (64 cols)
    const int m0   = blockIdx.y * MT;
    const int n0   = blockIdx.x * NT;

    const __half* Ag = g_qh + (size_t)(QOFF + m0) * DIM;  // x rows at queue tail
    const __half* Bg = g_qh + (size_t)n0 * DIM;

    // loaders: A 1024 16B-units (4/thread, row stride 32), B 2048 (8/thread)
    const int rL  = tid >> 3;          // base row 0..31
    const int c8L = tid & 7;           // 16B col group (constant across u)
    const uint32_t soL = swz128(rL, c8L);   // +u*4096 for row+32u (32u % 8 == 0)

#define LOAD_CHUNK(ck, stg) do { \
    uint32_t _sA = sbase + (uint32_t)(stg) * STG_BYTES; \
    uint32_t _sB = _sA + STG_A_BYTES; \
    int _ko = (ck) * KC + c8L * 8; \
    _Pragma("unroll") \
    for (int _u = 0; _u < 4; _u++) \
        cp16(_sA + soL + _u * 4096u, Ag + (size_t)(rL + 32 * _u) * DIM + _ko); \
    _Pragma("unroll") \
    for (int _u = 0; _u < 8; _u++) \
        cp16(_sB + soL + _u * 4096u, Bg + (size_t)(rL + 32 * _u) * DIM + _ko); \
    CP_COMMIT(); \
} while (0)

    // fragment addressing
    const int arow_lo = wm * 64 + (lane & 15);
    const int ac8_lo  = (lane >> 4);
    const int bg      = lane >> 3;
    const int brow_lo = wn * 64 + (bg >> 1) * 8 + (lane & 7);
    const int bc8_lo  = (bg & 1);

    uint32_t acc[4][8][2] = {};
    uint32_t af[4][4], bf[4][4];

    LOAD_CHUNK(0, 0);
    LOAD_CHUNK(1, 1);

    for (int c = 0; c < NCHUNK; c++) {
        const int stg = c & 1;
        CP_WAIT(1);
        __syncthreads();

        const uint32_t sA = sbase + (uint32_t)stg * STG_BYTES;
        const uint32_t sB = sA + STG_A_BYTES;

#pragma unroll
        for (int ks = 0; ks < 4; ks++) {
#pragma unroll
            for (int a = 0; a < 4; a++)
                ldm_x4(af[a], sA + swz128(arow_lo + a * 16, ks * 2 + ac8_lo));
#pragma unroll
            for (int b2 = 0; b2 < 4; b2++)
                ldm_x4(bf[b2], sB + swz128(brow_lo + b2 * 16, ks * 2 + bc8_lo));
#pragma unroll
            for (int a = 0; a < 4; a++)
#pragma unroll
                for (int b = 0; b < 8; b++)
                    mma16816h(acc[a][b], af[a], bf[b >> 1][(b & 1) * 2],
                                                bf[b >> 1][(b & 1) * 2 + 1]);
        }
        __syncthreads();   // all warps done reading stage before it is reloaded
        if (c + 2 < NCHUNK) LOAD_CHUNK(c + 2, stg);
    }

    // Epilogue: keys = qnorm[j] - 2*S; per-row top-2 over this warp's 64 cols.
    const int gid = lane >> 2, tig = lane & 3;
    const float INF = __int_as_float(0x7f800000);

    float qn[8][2];
#pragma unroll
    for (int b = 0; b < 8; b++) {
        int j = n0 + wn * 64 + b * 8 + tig * 2;
        qn[b][0] = g_qnorm[j];
        qn[b][1] = g_qnorm[j + 1];
    }

    float k1[8], k2[8]; int i1[8], i2[8];
#pragma unroll
    for (int s = 0; s < 8; s++) { k1[s] = k2[s] = INF; i1[s] = i2[s] = 0x7fffffff; }

#pragma unroll
    for (int a = 0; a < 4; a++)
#pragma unroll
        for (int b = 0; b < 8; b++) {
            int j = n0 + wn * 64 + b * 8 + tig * 2;
#pragma unroll
            for (int h = 0; h < 2; h++) {       // h=0: row gid, h=1: row gid+8
                int s = a * 2 + h;
                float2 v = __half22float2(*(const __half2*)&acc[a][b][h]);
#pragma unroll
                for (int e = 0; e < 2; e++) {
                    float key = fmaf(-2.f, e ? v.y : v.x, qn[b][e]);
                    int   jj  = j + e;
                    if (lex_less(key, jj, k1[s], i1[s])) {
                        k2[s] = k1[s]; i2[s] = i1[s]; k1[s] = key; i1[s] = jj;
                    } else if (lex_less(key, jj, k2[s], i2[s])) { k2[s] = key; i2[s] = jj; }
                }
            }
        }

#pragma unroll
    for (int off = 1; off <= 2; off <<= 1) {
#pragma unroll
        for (int s = 0; s < 8; s++) {
            float ok1 = __shfl_xor_sync(0xffffffffu, k1[s], off);
            int   oi1 = __shfl_xor_sync(0xffffffffu, i1[s], off);
            float ok2 = __shfl_xor_sync(0xffffffffu, k2[s], off);
            int   oi2 = __shfl_xor_sync(0xffffffffu, i2[s], off);
            merge2(k1[s], i1[s], k2[s], i2[s], ok1, oi1, ok2, oi2);
        }
    }

    if (tig == 0) {
        int ct = blockIdx.x * 4 + wn;
#pragma unroll
        for (int s = 0; s < 8; s++) {
            int row = m0 + wm * 64 + (s >> 1) * 16 + (s & 1) * 8 + gid;
            Top2 t; t.k1 = k1[s]; t.i1 = i1[s]; t.k2 = k2[s]; t.i2 = i2[s];
            g_partial[(size_t)row * PT + ct] = t;
        }
    }
}

// ---------------------------------------------------------------------------
// Kernel 3: per-row reduce to approx top-4, exact fp32 rescore, pick 2nd
// smallest, gather the queue row. One warp per row.
// ---------------------------------------------------------------------------
__global__ void __launch_bounds__(256) reduce_rescore_kernel(const float* __restrict__ x,
                                                             const float* __restrict__ qp,
                                                             float* __restrict__ out) {
    const int gw   = (blockIdx.x * blockDim.x + threadIdx.x) >> 5;  // row
    const int lane = threadIdx.x & 31;
    if (gw >= BATCH) return;
    const float INF = __int_as_float(0x7f800000);

    float ks[4]; int is[4];
#pragma unroll
    for (int q = 0; q < 4; q++) { ks[q] = INF; is[q] = 0x7fffffff; }

    const Top2* p = g_partial + (size_t)gw * PT;
    for (int t = lane; t < PT; t += 32) {
        Top2 o = p[t];
        insert4(ks, is, o.k1, o.i1);
        insert4(ks, is, o.k2, o.i2);
    }
#pragma unroll
    for (int off = 16; off; off >>= 1) {
        float ok[4]; int oi[4];
#pragma unroll
        for (int q = 0; q < 4; q++) {
            ok[q] = __shfl_xor_sync(0xffffffffu, ks[q], off);
            oi[q] = __shfl_xor_sync(0xffffffffu, is[q], off);
        }
#pragma unroll
        for (int q = 0; q < 4; q++) insert4(ks, is, ok[q], oi[q]);
    }

    // exact fp32 rescore of the 4 candidates
    const float* xr = x + (size_t)gw * DIM;
    float ek[4];
#pragma unroll
    for (int cdx = 0; cdx < 4; cdx++) {
        const float* qr = queue_row(x, qp, is[cdx]);
        float s = 0.f;
#pragma unroll
        for (int kk = 0; kk < 4; kk++) {
            int k = (lane + 32 * kk) * 4;
            float4 a = *(const float4*)(xr + k);
            float4 b = *(const float4*)(qr + k);
            s += a.x * b.x + a.y * b.y + a.z * b.z + a.w * b.w;
        }
#pragma unroll
        for (int o = 16; o; o >>= 1) s += __shfl_xor_sync(0xffffffffu, s, o);
        ek[cdx] = g_qnorm[is[cdx]] - 2.f * s;
    }
    int best = 0;
#pragma unroll
    for (int c = 1; c < 4; c++) if (lex_less(ek[c], is[c], ek[best], is[best])) best = c;
    int sec = (best == 0) ? 1 : 0;
#pragma unroll
    for (int c = 0; c < 4; c++)
        if (c != best && lex_less(ek[c], is[c], ek[sec], is[sec])) sec = c;
    const int nn = is[sec];

    const float4* src = (const float4*)queue_row(x, qp, nn);
    float4*       dst = (float4*)(out + (size_t)gw * DIM);
#pragma unroll
    for (int kk = 0; kk < 4; kk++) dst[lane + 32 * kk] = src[lane + 32 * kk];
}

// ---------------------------------------------------------------------------
extern "C" void kernel_launch(void* const* d_in, const int* in_sizes, int n_in,
                              void* d_out, int out_size) {
    const float* x   = (const float*)d_in[0];   // (1024, 512)
    const float* qp  = (const float*)d_in[1];   // (32768, 512)
    float*       out = (float*)d_out;           // (1024, 512)

    cudaFuncSetAttribute(mma_top2_kernel,
                         cudaFuncAttributeMaxDynamicSharedMemorySize, SMEM_BYTES);

    prep_kernel<<<QSZ / 8, 256>>>(x, qp);

    dim3 grid(NTILES, MTILES);                  // (128, 8)
    mma_top2_kernel<<<grid, 256, SMEM_BYTES>>>();

    reduce_rescore_kernel<<<BATCH / 8, 256>>>(x, qp, out);
}